// round 3
// baseline (speedup 1.0000x reference)
#include <cuda_runtime.h>
#include <cuda_fp16.h>
#include <cstdint>

// ============================ configuration ============================
// 128 CTAs (one wave), 256 threads (8 warps: 2 M-rows x 4 N-cols of warps).
// Per CTA: M=128 batch rows, N=H=256, K=H=256 (+1 aug k-tile of 16).
// h kept in SMEM as pre-packed mma A-fragments; U as pre-packed B-fragments.
#define NUM_CTAS 128
#define THREADS  256
#define T_STEPS  79
#define TCOLS    79

// B-fragment region: [kt 0..16][nt 0..31][lane][2x u32] = 17*32*256 B
#define SMEM_BFRAG   0
#define BFRAG_BYTES  (17 * 32 * 256)
// A(h)-fragment region: [mt 0..7][kt 0..16][lane][4x u32] = 8*17*512 B
#define SMEM_HFRAG   BFRAG_BYTES
#define HFRAG_BYTES  (8 * 17 * 512)
#define SMEM_TOTAL   (BFRAG_BYTES + HFRAG_BYTES)   // 208896 B

// ============================ helpers ============================
static __device__ __forceinline__ uint32_t pk(float lo, float hi) {
    uint32_t r;
    asm("cvt.rn.f16x2.f32 %0, %1, %2;" : "=r"(r) : "f"(hi), "f"(lo));
    return r;
}
static __device__ __forceinline__ uint32_t pkrelu(float lo, float hi) {
    uint32_t r;
    asm("cvt.rn.relu.f16x2.f32 %0, %1, %2;" : "=r"(r) : "f"(hi), "f"(lo));
    return r;
}
static __device__ __forceinline__ float f16hi(float v) {   // v rounded to fp16
    return __half2float(__float2half_rn(v));
}

#define MMA16816(c, a, b) \
    asm volatile("mma.sync.aligned.m16n8k16.row.col.f32.f16.f16.f32 " \
        "{%0,%1,%2,%3}, {%4,%5,%6,%7}, {%8,%9}, {%0,%1,%2,%3};" \
        : "+f"((c)[0]), "+f"((c)[1]), "+f"((c)[2]), "+f"((c)[3]) \
        : "r"((a).x), "r"((a).y), "r"((a).z), "r"((a).w), "r"((b).x), "r"((b).y))

// byte offsets into the fragment regions
static __device__ __forceinline__ uint32_t bfrag_off(int kt, int nt_g, int lane) {
    return SMEM_BFRAG + (uint32_t)((kt * 32 + nt_g) << 8) + (uint32_t)(lane << 3);
}
static __device__ __forceinline__ uint32_t hfrag_off(int mt_g, int kt, int lane) {
    return SMEM_HFRAG + (uint32_t)((mt_g * 17 + kt) << 9) + (uint32_t)(lane << 4);
}

// ---- build B fragments from a row-major fp32 matrix M[256][256] ----
// B[k][n] = M[k][n] as fp16. lo=0: round(v). lo=1: round(v - round(v)).
// m16n8k16 B frag (col-major): lane holds (k0,n),(k0+1,n) and (k0+8,n),(k0+9,n),
// k0 = kt*16 + (lane&3)*2, n = nt*8 + lane/4.
static __device__ __forceinline__ void fill_B_frags(char* smem, const float* __restrict__ M, int lo) {
    const int lane = threadIdx.x & 31;
    const int w    = threadIdx.x >> 5;
    const int n_in = (lane >> 2);
    const int kof  = (lane & 3) * 2;
    for (int s = w; s < 512; s += 8) {                // kt 0..15, nt 0..31
        const int kt = s >> 5, nt = s & 31;
        const int k0 = kt * 16 + kof;
        const int n  = nt * 8 + n_in;
        float v00 = __ldg(M + (k0    ) * 256 + n);
        float v01 = __ldg(M + (k0 + 1) * 256 + n);
        float v10 = __ldg(M + (k0 + 8) * 256 + n);
        float v11 = __ldg(M + (k0 + 9) * 256 + n);
        if (lo) {
            v00 -= f16hi(v00); v01 -= f16hi(v01);
            v10 -= f16hi(v10); v11 -= f16hi(v11);
        }
        uint2 b;
        b.x = pk(v00, v01);
        b.y = pk(v10, v11);
        *reinterpret_cast<uint2*>(smem + bfrag_off(kt, nt, lane)) = b;
    }
}

// aug B row value: k0..2 = Win_hi, k3..5 = Win_lo, k6..8 = Win_hi, k9 = b_rnn, else 0
static __device__ __forceinline__ float baug_val(int k, int n,
                                                const float* __restrict__ W_in,
                                                const float* __restrict__ b_rnn) {
    if (k < 3)  return f16hi(__ldg(W_in + k * 256 + n));
    if (k < 6)  { float v = __ldg(W_in + (k - 3) * 256 + n); return v - f16hi(v); }
    if (k < 9)  return f16hi(__ldg(W_in + (k - 6) * 256 + n));
    if (k == 9) return __ldg(b_rnn + n);
    return 0.0f;
}

// aug A slot value: k0..2 = x_hi, k3..5 = x_lo, k6..8 = x_hi, k9 = 1, else 0.
// Pairing with aug B gives xh*Wh + xl*Wl(? no:) — see mapping below:
//   A k0..2 (xh) * B k0..2 (Wh)  +  A k3..5 (xl) * B k3..5 (Wl is at 3..5)
//   A k6..8 (xh) * B k6..8 (Wh)? -> that would double-count.
// Correct scheme (matches baug_val above):
//   A: k0..2 = xh, k3..5 = xh, k6..8 = xl, k9 = 1
//   B: k0..2 = Wh, k3..5 = Wl, k6..8 = Wh, k9 = b_rnn
//   sum = xh*Wh + xh*Wl + xl*Wh + b  =  x*W + b - xl*Wl  (|xl*Wl| < 1e-7)
static __device__ __forceinline__ float aaug_val(int k, float xh0, float xh1, float xh2,
                                                 float xl0, float xl1, float xl2) {
    switch (k) {
        case 0: return xh0;  case 1: return xh1;  case 2: return xh2;
        case 3: return xh0;  case 4: return xh1;  case 5: return xh2;
        case 6: return xl0;  case 7: return xl1;  case 8: return xl2;
        case 9: return 1.0f;
        default: return 0.0f;
    }
}

// ============================ kernel ============================
__global__ void __launch_bounds__(THREADS, 1)
rnn_hmma_kernel(const float* __restrict__ x0, const float* __restrict__ x1,
                const float* __restrict__ x2, const float* __restrict__ W_in,
                const float* __restrict__ U,  const float* __restrict__ b_rnn,
                const float* __restrict__ W_d, const float* __restrict__ b_d,
                float* __restrict__ out)
{
    extern __shared__ __align__(128) char smem[];
    const int tid  = threadIdx.x;
    const int lane = tid & 31;
    const int wid  = tid >> 5;
    const int wm   = wid >> 2;          // 0..1  (M split)
    const int wn   = wid & 3;           // 0..3  (N split)
    const int rowBase = blockIdx.x * 128;

    // -------- init: U -> B frags; aug B; aug A for step 0 --------
    fill_B_frags(smem, U, 0);

    // aug B (kt = 16): s in [512, 544)
    {
        const int n_in = (lane >> 2);
        const int kof  = (lane & 3) * 2;
        for (int s = 512 + (tid >> 5); s < 544; s += 8) {
            const int nt = s & 31;
            const int n  = nt * 8 + n_in;
            uint2 b;
            b.x = pk(baug_val(kof,     n, W_in, b_rnn), baug_val(kof + 1, n, W_in, b_rnn));
            b.y = pk(baug_val(kof + 8, n, W_in, b_rnn), baug_val(kof + 9, n, W_in, b_rnn));
            *reinterpret_cast<uint2*>(smem + bfrag_off(16, nt, lane)) = b;
        }
    }

    // aug A frag writer (per step). tid -> (mt_g = tid>>5, lane). Rows r0, r0+8.
    const int aug_mt   = tid >> 5;
    const int aug_r0   = aug_mt * 16 + (lane >> 2);
    const int aug_kof  = (lane & 3) * 2;
    const int aug_g0   = (rowBase + aug_r0) * TCOLS;
    const int aug_g1   = (rowBase + aug_r0 + 8) * TCOLS;

    {   // step 0 uses original time column 78
        const int tc = 78;
        float p0 = __ldg(x0 + aug_g0 + tc), p1 = __ldg(x1 + aug_g0 + tc), p2 = __ldg(x2 + aug_g0 + tc);
        float q0 = __ldg(x0 + aug_g1 + tc), q1 = __ldg(x1 + aug_g1 + tc), q2 = __ldg(x2 + aug_g1 + tc);
        float ph0 = f16hi(p0), ph1 = f16hi(p1), ph2 = f16hi(p2);
        float qh0 = f16hi(q0), qh1 = f16hi(q1), qh2 = f16hi(q2);
        uint4 a;
        a.x = pk(aaug_val(aug_kof,     ph0, ph1, ph2, p0 - ph0, p1 - ph1, p2 - ph2),
                 aaug_val(aug_kof + 1, ph0, ph1, ph2, p0 - ph0, p1 - ph1, p2 - ph2));
        a.y = pk(aaug_val(aug_kof,     qh0, qh1, qh2, q0 - qh0, q1 - qh1, q2 - qh2),
                 aaug_val(aug_kof + 1, qh0, qh1, qh2, q0 - qh0, q1 - qh1, q2 - qh2));
        a.z = pk(aaug_val(aug_kof + 8, ph0, ph1, ph2, p0 - ph0, p1 - ph1, p2 - ph2),
                 aaug_val(aug_kof + 9, ph0, ph1, ph2, p0 - ph0, p1 - ph1, p2 - ph2));
        a.w = pk(aaug_val(aug_kof + 8, qh0, qh1, qh2, q0 - qh0, q1 - qh1, q2 - qh2),
                 aaug_val(aug_kof + 9, qh0, qh1, qh2, q0 - qh0, q1 - qh1, q2 - qh2));
        *reinterpret_cast<uint4*>(smem + hfrag_off(aug_mt, 16, lane)) = a;
    }
    __syncthreads();

    // ============================ 79 recurrent steps ============================
    float c[4][8][4];

#pragma unroll 1
    for (int t = 0; t < T_STEPS; ++t) {
        // prefetch next step's x (L2-resident); consumed in the epilogue
        float p0 = 0.f, p1 = 0.f, p2 = 0.f, q0 = 0.f, q1 = 0.f, q2 = 0.f;
        if (t < T_STEPS - 1) {
            const int tc = 77 - t;
            p0 = __ldg(x0 + aug_g0 + tc); p1 = __ldg(x1 + aug_g0 + tc); p2 = __ldg(x2 + aug_g0 + tc);
            q0 = __ldg(x0 + aug_g1 + tc); q1 = __ldg(x1 + aug_g1 + tc); q2 = __ldg(x2 + aug_g1 + tc);
        }

#pragma unroll
        for (int mt = 0; mt < 4; ++mt)
#pragma unroll
            for (int nt = 0; nt < 8; ++nt)
#pragma unroll
                for (int i = 0; i < 4; ++i) c[mt][nt][i] = 0.0f;

        // ---- MMA over K: h(t) tiles (skip at t==0 since h0 == 0), then aug ----
        if (t) {
#pragma unroll
            for (int kt = 0; kt < 16; ++kt) {
                uint4 a[4];
#pragma unroll
                for (int mt = 0; mt < 4; ++mt)
                    a[mt] = *reinterpret_cast<const uint4*>(smem + hfrag_off(wm * 4 + mt, kt, lane));
                uint2 b[8];
#pragma unroll
                for (int nt = 0; nt < 8; ++nt)
                    b[nt] = *reinterpret_cast<const uint2*>(smem + bfrag_off(kt, wn * 8 + nt, lane));
#pragma unroll
                for (int mt = 0; mt < 4; ++mt)
#pragma unroll
                    for (int nt = 0; nt < 8; ++nt)
                        MMA16816(c[mt][nt], a[mt], b[nt]);
            }
        }
        {   // aug k-tile (kt = 16): adds xp_t (+ bias)
            uint4 a[4];
#pragma unroll
            for (int mt = 0; mt < 4; ++mt)
                a[mt] = *reinterpret_cast<const uint4*>(smem + hfrag_off(wm * 4 + mt, 16, lane));
            uint2 b[8];
#pragma unroll
            for (int nt = 0; nt < 8; ++nt)
                b[nt] = *reinterpret_cast<const uint2*>(smem + bfrag_off(16, wn * 8 + nt, lane));
#pragma unroll
            for (int mt = 0; mt < 4; ++mt)
#pragma unroll
                for (int nt = 0; nt < 8; ++nt)
                    MMA16816(c[mt][nt], a[mt], b[nt]);
        }

        __syncthreads();   // all reads of h(t) fragments complete

        // ---- epilogue: h(t+1) = relu(D) as fp16 A-fragments ----
        // D tile (mt_g, nt_g) cols [8*nt_g, 8*nt_g+8) -> A frag kt = nt_g>>1, half = nt_g&1.
        // pack(c0,c1) -> a0/a2 slot, pack(c2,c3) -> a1/a3 slot (identical lane mapping).
#pragma unroll
        for (int mt = 0; mt < 4; ++mt) {
            const int mt_g = wm * 4 + mt;
#pragma unroll
            for (int nt = 0; nt < 8; ++nt) {
                const int nt_g = wn * 8 + nt;
                uint2 hpair;
                hpair.x = pkrelu(c[mt][nt][0], c[mt][nt][1]);
                hpair.y = pkrelu(c[mt][nt][2], c[mt][nt][3]);
                *reinterpret_cast<uint2*>(smem + hfrag_off(mt_g, nt_g >> 1, lane)
                                          + ((nt_g & 1) << 3)) = hpair;
            }
        }

        if (t < T_STEPS - 1) {   // write aug A fragments for step t+1
            float ph0 = f16hi(p0), ph1 = f16hi(p1), ph2 = f16hi(p2);
            float qh0 = f16hi(q0), qh1 = f16hi(q1), qh2 = f16hi(q2);
            float pl0 = p0 - ph0, pl1 = p1 - ph1, pl2 = p2 - ph2;
            float ql0 = q0 - qh0, ql1 = q1 - qh1, ql2 = q2 - qh2;
            uint4 a;
            a.x = pk(aaug_val(aug_kof,     ph0, ph1, ph2, pl0, pl1, pl2),
                     aaug_val(aug_kof + 1, ph0, ph1, ph2, pl0, pl1, pl2));
            a.y = pk(aaug_val(aug_kof,     qh0, qh1, qh2, ql0, ql1, ql2),
                     aaug_val(aug_kof + 1, qh0, qh1, qh2, ql0, ql1, ql2));
            a.z = pk(aaug_val(aug_kof + 8, ph0, ph1, ph2, pl0, pl1, pl2),
                     aaug_val(aug_kof + 9, ph0, ph1, ph2, pl0, pl1, pl2));
            a.w = pk(aaug_val(aug_kof + 8, qh0, qh1, qh2, ql0, ql1, ql2),
                     aaug_val(aug_kof + 9, qh0, qh1, qh2, ql0, ql1, ql2));
            *reinterpret_cast<uint4*>(smem + hfrag_off(aug_mt, 16, lane)) = a;
        }

        __syncthreads();   // h(t+1) fragments visible
    }

    // ============================ final: out = hT @ W_d + b_d ============================
    // Two exact passes: W_d split hi + lo (fp16), reusing the B-fragment region.
    fill_B_frags(smem, W_d, 0);
    __syncthreads();

#pragma unroll
    for (int mt = 0; mt < 4; ++mt)
#pragma unroll
        for (int nt = 0; nt < 8; ++nt)
#pragma unroll
            for (int i = 0; i < 4; ++i) c[mt][nt][i] = 0.0f;

#pragma unroll
    for (int kt = 0; kt < 16; ++kt) {
        uint4 a[4];
#pragma unroll
        for (int mt = 0; mt < 4; ++mt)
            a[mt] = *reinterpret_cast<const uint4*>(smem + hfrag_off(wm * 4 + mt, kt, lane));
        uint2 b[8];
#pragma unroll
        for (int nt = 0; nt < 8; ++nt)
            b[nt] = *reinterpret_cast<const uint2*>(smem + bfrag_off(kt, wn * 8 + nt, lane));
#pragma unroll
        for (int mt = 0; mt < 4; ++mt)
#pragma unroll
            for (int nt = 0; nt < 8; ++nt)
                MMA16816(c[mt][nt], a[mt], b[nt]);
    }

    __syncthreads();               // pass-1 B reads done
    fill_B_frags(smem, W_d, 1);    // lo residuals
    __syncthreads();

#pragma unroll
    for (int kt = 0; kt < 16; ++kt) {
        uint4 a[4];
#pragma unroll
        for (int mt = 0; mt < 4; ++mt)
            a[mt] = *reinterpret_cast<const uint4*>(smem + hfrag_off(wm * 4 + mt, kt, lane));
        uint2 b[8];
#pragma unroll
        for (int nt = 0; nt < 8; ++nt)
            b[nt] = *reinterpret_cast<const uint2*>(smem + bfrag_off(kt, wn * 8 + nt, lane));
#pragma unroll
        for (int mt = 0; mt < 4; ++mt)
#pragma unroll
            for (int nt = 0; nt < 8; ++nt)
                MMA16816(c[mt][nt], a[mt], b[nt]);
    }

    // ---- store: out[row][col] = D + b_d ----
    {
        const int cb_base = wn * 64 + (lane & 3) * 2;
        float2 bdv[8];
#pragma unroll
        for (int nt = 0; nt < 8; ++nt)
            bdv[nt] = *reinterpret_cast<const float2*>(b_d + cb_base + nt * 8);

        const int r_base = rowBase + wm * 64 + (lane >> 2);
#pragma unroll
        for (int mt = 0; mt < 4; ++mt) {
            const size_t r0 = (size_t)(r_base + mt * 16) * 256;
            const size_t r1 = r0 + 8 * 256;
#pragma unroll
            for (int nt = 0; nt < 8; ++nt) {
                const int cb = cb_base + nt * 8;
                float2 v0, v1;
                v0.x = c[mt][nt][0] + bdv[nt].x;
                v0.y = c[mt][nt][1] + bdv[nt].y;
                v1.x = c[mt][nt][2] + bdv[nt].x;
                v1.y = c[mt][nt][3] + bdv[nt].y;
                *reinterpret_cast<float2*>(out + r0 + cb) = v0;
                *reinterpret_cast<float2*>(out + r1 + cb) = v1;
            }
        }
    }
}

// ============================ launch ============================
extern "C" void kernel_launch(void* const* d_in, const int* in_sizes, int n_in,
                              void* d_out, int out_size) {
    (void)in_sizes; (void)n_in; (void)out_size;
    cudaFuncSetAttribute(rnn_hmma_kernel,
                         cudaFuncAttributeMaxDynamicSharedMemorySize, SMEM_TOTAL);
    rnn_hmma_kernel<<<NUM_CTAS, THREADS, SMEM_TOTAL>>>(
        (const float*)d_in[0], (const float*)d_in[1], (const float*)d_in[2],
        (const float*)d_in[3], (const float*)d_in[4], (const float*)d_in[5],
        (const float*)d_in[6], (const float*)d_in[7],
        (float*)d_out);
}